// round 1
// baseline (speedup 1.0000x reference)
#include <cuda_runtime.h>
#include <cfloat>
#include <cstdint>

#define NN 204800
#define EE 1638400
#define BB 4096
#define KK 10
#define HH 64
#define FIN 128
#define FEATW 192

// ---------------- scratch (static device globals; no allocation) -------------
__device__ float g_dinv[NN];
__device__ float g_tmp[NN * HH];      // h = in @ W   (pre-aggregation)
__device__ float g_agg[NN * HH];      // aggregated
__device__ float g_feat[NN * FEATW];  // [x1 | x2 | x3]
__device__ float g_rowmax[NN];
__device__ int   g_sel[BB * KK];
__device__ float g_pooled[BB * KK * FEATW];

// ---------------- degree / norm ---------------------------------------------
__global__ void k_deg_init() {
    int n = blockIdx.x * blockDim.x + threadIdx.x;
    if (n < NN) g_dinv[n] = 1.0f;   // self-loop contributes 1
}
__global__ void k_deg_count(const int* __restrict__ ei) {
    int e = blockIdx.x * blockDim.x + threadIdx.x;
    if (e < EE) atomicAdd(&g_dinv[ei[EE + e]], 1.0f);   // count targets (col)
}
__global__ void k_deg_finish() {
    int n = blockIdx.x * blockDim.x + threadIdx.x;
    if (n < NN) g_dinv[n] = rsqrtf(g_dinv[n]);
}

// ---------------- GEMM: tmp[N,64] = in[N,K] @ W[K,64] ------------------------
// 256 threads/block, 256 rows/block. 8x8 micro-tile per thread.
__global__ void k_gemm(const float* __restrict__ xext, int mode, int off,
                       int ldin, int K, const float* __restrict__ W)
{
    __shared__ float sW[FIN * HH];   // up to 128*64 = 32KB
    const float* in = mode ? (g_feat + off) : xext;

    for (int i = threadIdx.x; i < K * HH; i += 256) sW[i] = W[i];
    __syncthreads();

    int tx = threadIdx.x & 7;        // col group  c0 = tx*8
    int ty = threadIdx.x >> 3;       // row group  r0 = ty*8
    int rowBase = blockIdx.x * 256 + ty * 8;

    const float* rp[8];
#pragma unroll
    for (int r = 0; r < 8; r++) rp[r] = in + (size_t)(rowBase + r) * ldin;

    float acc[8][8];
#pragma unroll
    for (int r = 0; r < 8; r++)
#pragma unroll
        for (int c = 0; c < 8; c++) acc[r][c] = 0.0f;

    int c0 = tx * 8;
    for (int k = 0; k < K; k++) {
        float4 w0 = *(const float4*)&sW[k * HH + c0];
        float4 w1 = *(const float4*)&sW[k * HH + c0 + 4];
#pragma unroll
        for (int r = 0; r < 8; r++) {
            float xv = rp[r][k];
            acc[r][0] += xv * w0.x; acc[r][1] += xv * w0.y;
            acc[r][2] += xv * w0.z; acc[r][3] += xv * w0.w;
            acc[r][4] += xv * w1.x; acc[r][5] += xv * w1.y;
            acc[r][6] += xv * w1.z; acc[r][7] += xv * w1.w;
        }
    }
#pragma unroll
    for (int r = 0; r < 8; r++) {
        float* o = &g_tmp[(size_t)(rowBase + r) * HH + c0];
        *(float4*)o       = make_float4(acc[r][0], acc[r][1], acc[r][2], acc[r][3]);
        *(float4*)(o + 4) = make_float4(acc[r][4], acc[r][5], acc[r][6], acc[r][7]);
    }
}

// ---------------- aggregation -----------------------------------------------
__global__ void k_agg_init() {   // agg = tmp * dinv^2  (self loop)
    int t = blockIdx.x * blockDim.x + threadIdx.x;
    if (t >= NN * HH) return;
    int n = t >> 6;
    float d = g_dinv[n];
    g_agg[t] = g_tmp[t] * d * d;
}
__global__ void k_scatter(const int* __restrict__ ei) {
    long long t = (long long)blockIdx.x * blockDim.x + threadIdx.x;
    if (t >= (long long)EE * 16) return;
    int e  = (int)(t >> 4);
    int c4 = ((int)t & 15) * 4;
    int r  = ei[e];
    int c  = ei[EE + e];
    float coef = g_dinv[r] * g_dinv[c];
    float4 v = *(const float4*)&g_tmp[(size_t)r * HH + c4];
    float* dst = &g_agg[(size_t)c * HH + c4];
    atomicAdd(dst + 0, v.x * coef);
    atomicAdd(dst + 1, v.y * coef);
    atomicAdd(dst + 2, v.z * coef);
    atomicAdd(dst + 3, v.w * coef);
}
__global__ void k_finalize(const float* __restrict__ b, int off) {
    int t = blockIdx.x * blockDim.x + threadIdx.x;
    if (t >= NN * HH) return;
    int n = t >> 6, c = t & 63;
    g_feat[(size_t)n * FEATW + off + c] = tanhf(g_agg[t] + b[c]);
}

// ---------------- row max (warp/row) -----------------------------------------
__global__ void k_rowmax() {
    int warp = (blockIdx.x * blockDim.x + threadIdx.x) >> 5;
    int lane = threadIdx.x & 31;
    if (warp >= NN) return;
    const float* f = &g_feat[(size_t)warp * FEATW];
    float m = -FLT_MAX;
    for (int i = lane; i < FEATW; i += 32) m = fmaxf(m, f[i]);
#pragma unroll
    for (int o = 16; o; o >>= 1) m = fmaxf(m, __shfl_xor_sync(0xffffffffu, m, o));
    if (lane == 0) g_rowmax[warp] = m;
}

// ---------------- top-K per graph (stable, matches lexsort) ------------------
__global__ void k_select() {
    int g = blockIdx.x * blockDim.x + threadIdx.x;
    if (g >= BB) return;
    const float* rm = &g_rowmax[g * 50];
    unsigned long long used = 0ull;
#pragma unroll 1
    for (int k = 0; k < KK; k++) {
        float best = -FLT_MAX; int bi = 0;
        for (int i = 0; i < 50; i++) {
            if ((used >> i) & 1ull) continue;
            float v = rm[i];
            if (v > best) { best = v; bi = i; }
        }
        used |= 1ull << bi;
        g_sel[g * KK + k] = g * 50 + bi;
    }
}

// ---------------- sort selected rows (warp/row bitonic, 256 w/ +inf pad) -----
__global__ void k_sortrows() {
    __shared__ float s[8][256];
    int warp = threadIdx.x >> 5, lane = threadIdx.x & 31;
    int r = blockIdx.x * 8 + warp;            // r < BB*KK
    int node = g_sel[r];
    const float* f = &g_feat[(size_t)node * FEATW];
    for (int i = lane; i < FEATW; i += 32) s[warp][i] = f[i];
    for (int i = FEATW + lane; i < 256; i += 32) s[warp][i] = FLT_MAX;
    __syncwarp();
    for (int k = 2; k <= 256; k <<= 1) {
        for (int j = k >> 1; j > 0; j >>= 1) {
            for (int i = lane; i < 256; i += 32) {
                int ixj = i ^ j;
                if (ixj > i) {
                    bool up = ((i & k) == 0);
                    float a = s[warp][i], b = s[warp][ixj];
                    if ((a > b) == up) { s[warp][i] = b; s[warp][ixj] = a; }
                }
            }
            __syncwarp();
        }
    }
    float* out = &g_pooled[(size_t)r * FEATW];
    for (int i = lane; i < FEATW; i += 32) out[i] = s[warp][i];
}

// ---------------- CNN head: one block per graph ------------------------------
__global__ void k_cnn(const float* __restrict__ Wc1, const float* __restrict__ bc1,
                      const float* __restrict__ Wc2, const float* __restrict__ bc2,
                      const float* __restrict__ Wf,  const float* __restrict__ bf,
                      float* c_out, float* xf_out)
{
    __shared__ float s_p[KK * FEATW];     // 1920
    __shared__ float s_w1[32 * KK * 4];   // 1280
    __shared__ float s_w2[64 * 32 * 3];   // 6144
    __shared__ float s_a[32 * 48];        // 1536
    __shared__ float s_b[32 * 12];        // 384
    __shared__ float s_y[64 * 4];         // 256
    __shared__ float s_xf[64];

    int g = blockIdx.x, tid = threadIdx.x;
    const float* p = &g_pooled[(size_t)g * KK * FEATW];
    for (int i = tid; i < KK * FEATW; i += 128) s_p[i] = p[i];
    for (int i = tid; i < 32 * KK * 4; i += 128) s_w1[i] = Wc1[i];
    for (int i = tid; i < 64 * 32 * 3; i += 128) s_w2[i] = Wc2[i];
    __syncthreads();

    // conv1: [10,192] -> [32,48], kernel 4, stride 4, then relu
    for (int idx = tid; idx < 32 * 48; idx += 128) {
        int oc = idx / 48, t = idx % 48;
        float acc = bc1[oc];
#pragma unroll
        for (int ic = 0; ic < KK; ic++) {
            const float* pp = &s_p[ic * FEATW + t * 4];
            const float* ww = &s_w1[oc * (KK * 4) + ic * 4];
            acc += pp[0]*ww[0] + pp[1]*ww[1] + pp[2]*ww[2] + pp[3]*ww[3];
        }
        s_a[idx] = fmaxf(acc, 0.0f);
    }
    __syncthreads();
    // maxpool 4 -> [32,12]
    for (int idx = tid; idx < 32 * 12; idx += 128) {
        int oc = idx / 12, t = idx % 12;
        const float* a = &s_a[oc * 48 + t * 4];
        s_b[idx] = fmaxf(fmaxf(a[0], a[1]), fmaxf(a[2], a[3]));
    }
    __syncthreads();
    // conv2: [32,12] -> [64,4], kernel 3, stride 3, relu
    for (int idx = tid; idx < 64 * 4; idx += 128) {
        int oc = idx / 4, t = idx % 4;
        float acc = bc2[oc];
#pragma unroll
        for (int ic = 0; ic < 32; ic++) {
            const float* bb = &s_b[ic * 12 + t * 3];
            const float* ww = &s_w2[oc * 96 + ic * 3];
            acc += bb[0]*ww[0] + bb[1]*ww[1] + bb[2]*ww[2];
        }
        s_y[idx] = fmaxf(acc, 0.0f);
    }
    __syncthreads();
    // maxpool 4 -> [64] = xf
    if (tid < 64) {
        const float* y = &s_y[tid * 4];
        float v = fmaxf(fmaxf(y[0], y[1]), fmaxf(y[2], y[3]));
        s_xf[tid] = v;
        if (xf_out) xf_out[(size_t)g * 64 + tid] = v;
    }
    __syncthreads();
    // fc: c = relu(xf) @ Wf + bf   (xf >= 0 already, relu is identity)
    if (tid < 10 && c_out) {
        float acc = bf[tid];
#pragma unroll
        for (int i = 0; i < 64; i++) acc += fmaxf(s_xf[i], 0.0f) * Wf[i * 10 + tid];
        c_out[(size_t)g * 10 + tid] = acc;
    }
}

// ---------------- launcher ----------------------------------------------------
extern "C" void kernel_launch(void* const* d_in, const int* in_sizes, int n_in,
                              void* d_out, int out_size)
{
    const float* x   = (const float*)d_in[0];
    const int*   ei  = (const int*)  d_in[1];
    // d_in[2] = batch (structure is fixed: 50 nodes/graph) — unused
    const float* W1  = (const float*)d_in[3];
    const float* b1  = (const float*)d_in[4];
    const float* W2  = (const float*)d_in[5];
    const float* b2  = (const float*)d_in[6];
    const float* W3  = (const float*)d_in[7];
    const float* b3  = (const float*)d_in[8];
    const float* Wc1 = (const float*)d_in[9];
    const float* bc1 = (const float*)d_in[10];
    const float* Wc2 = (const float*)d_in[11];
    const float* bc2 = (const float*)d_in[12];
    const float* Wf  = (const float*)d_in[13];
    const float* bf  = (const float*)d_in[14];

    float* out = (float*)d_out;
    float* c_out  = nullptr;
    float* xf_out = nullptr;
    if (out_size >= BB * 74) { c_out = out; xf_out = out + BB * 10; }
    else if (out_size == BB * 10) { c_out = out; }
    else { xf_out = out; }

    // degrees / normalization
    k_deg_init <<<(NN + 255) / 256, 256>>>();
    k_deg_count<<<(EE + 255) / 256, 256>>>(ei);
    k_deg_finish<<<(NN + 255) / 256, 256>>>();

    const int NB_ROWS = NN / 256;                 // 800
    const int NB_NH   = (NN * HH) / 256;          // 51200
    const long long SC = (long long)EE * 16;
    const int NB_SC   = (int)((SC + 255) / 256);  // 102400

    // layer 1: K=128, input = x
    k_gemm    <<<NB_ROWS, 256>>>(x, 0, 0, FIN, FIN, W1);
    k_agg_init<<<NB_NH, 256>>>();
    k_scatter <<<NB_SC, 256>>>(ei);
    k_finalize<<<NB_NH, 256>>>(b1, 0);

    // layer 2: K=64, input = feat[:,0:64]
    k_gemm    <<<NB_ROWS, 256>>>(nullptr, 1, 0, FEATW, HH, W2);
    k_agg_init<<<NB_NH, 256>>>();
    k_scatter <<<NB_SC, 256>>>(ei);
    k_finalize<<<NB_NH, 256>>>(b2, 64);

    // layer 3: K=64, input = feat[:,64:128]
    k_gemm    <<<NB_ROWS, 256>>>(nullptr, 1, 64, FEATW, HH, W3);
    k_agg_init<<<NB_NH, 256>>>();
    k_scatter <<<NB_SC, 256>>>(ei);
    k_finalize<<<NB_NH, 256>>>(b3, 128);

    // sort-pooling
    k_rowmax  <<<(NN * 32 + 255) / 256, 256>>>();
    k_select  <<<(BB + 255) / 256, 256>>>();
    k_sortrows<<<(BB * KK) / 8, 256>>>();

    // CNN head + fc
    k_cnn<<<BB, 128>>>(Wc1, bc1, Wc2, bc2, Wf, bf, c_out, xf_out);
}